// round 10
// baseline (speedup 1.0000x reference)
#include <cuda_runtime.h>
#include <math.h>

// ---------------------------------------------------------------------------
// BinaryCQV end-to-end: 2-warp-per-sample statevector sim, f32x2-packed.
// 10-bit old index: bit0 = warp, bit1 = packed-half, bits2-4 = pack index k,
// bits5-9 = lane. State: XR[8], XI[8] u64, each = (amp(2k), amp(2k+1)).
// CNOT-free GF(2) frame tracking + fused SU(2) gates; all gate FMAs are
// packed fma.rn.f32x2 (FFMA2), halving FMA issue slots.
// ---------------------------------------------------------------------------

#define FULLMASK 0xffffffffu
#define PI_F 3.14159265358979323846f
#define BATCH 2048
#define INPUT_DIM 49

typedef unsigned long long u64;

__device__ __forceinline__ u64 pk2(float lo, float hi) {
    u64 r; asm("mov.b64 %0, {%1, %2};" : "=l"(r) : "f"(lo), "f"(hi)); return r;
}
__device__ __forceinline__ void up2(u64 v, float& lo, float& hi) {
    asm("mov.b64 {%0, %1}, %2;" : "=f"(lo), "=f"(hi) : "l"(v));
}
__device__ __forceinline__ u64 sw2(u64 v) {
    float lo, hi; up2(v, lo, hi); return pk2(hi, lo);
}
__device__ __forceinline__ u64 f2fma(u64 a, u64 b, u64 c) {
    u64 d; asm("fma.rn.f32x2 %0, %1, %2, %3;" : "=l"(d) : "l"(a), "l"(b), "l"(c)); return d;
}
__device__ __forceinline__ u64 f2mul(u64 a, u64 b) {
    u64 d; asm("mul.rn.f32x2 %0, %1, %2;" : "=l"(d) : "l"(a), "l"(b)); return d;
}

// per-gate packed coefficient bundle
struct GC { u64 AR2, BI2, NBI2, CA0, CA1, CB0, CB1; };

template<int RW, int RH, int RK, int RL>
__device__ __forceinline__ GC make_gc(float Ar, float Ai, float Br, float Bi,
                                      int lane, int w) {
    int lp = 0;
    if (RL) lp = __popc(lane & RL) & 1;
    if (RW) lp ^= w;
    const float Ai0 = lp ? Ai : -Ai, Ai1 = -Ai0;
    const float Br0 = lp ? Br : -Br, Br1 = -Br0;
    GC g;
    g.AR2  = pk2(Ar, Ar);
    g.BI2  = pk2(Bi, Bi);
    g.NBI2 = pk2(-Bi, -Bi);
    if (RH) {
        g.CA0 = pk2(Ai0, Ai1); g.CA1 = pk2(Ai1, Ai0);
        g.CB0 = pk2(Br0, Br1); g.CB1 = pk2(Br1, Br0);
    } else {
        g.CA0 = pk2(Ai0, Ai0); g.CA1 = pk2(Ai1, Ai1);
        g.CB0 = pk2(Br0, Br0); g.CB1 = pk2(Br1, Br1);
    }
    return g;
}

// packed element update:
//   nr = Ar*xr + aK*xi + bK*pr - Bi*pi ; ni = Ar*xi - aK*xr + bK*pi + Bi*pr
__device__ __forceinline__ void upd(u64& xr, u64& xi, u64 pr, u64 pi,
                                    const GC& g, bool p) {
    const u64 aK  = p ? g.CA1 : g.CA0;
    const u64 naK = p ? g.CA0 : g.CA1;
    const u64 bK  = p ? g.CB1 : g.CB0;
    const u64 nr = f2fma(g.NBI2, pi, f2fma(bK, pr, f2fma(aK,  xi, f2mul(g.AR2, xr))));
    const u64 ni = f2fma(g.BI2,  pr, f2fma(bK, pi, f2fma(naK, xr, f2mul(g.AR2, xi))));
    xr = nr; xi = ni;
}

// general packed gate: mask splits MK (pack xor), ML (lane xor); role RW/RH/RK/RL.
template<int MK, int ML, int RW, int RH, int RK, int RL>
__device__ __forceinline__ void g_packed(u64 (&XR)[8], u64 (&XI)[8],
                                         float Ar, float Ai, float Br, float Bi,
                                         int lane, int w) {
    const GC g = make_gc<RW, RH, RK, RL>(Ar, Ai, Br, Bi, lane, w);
    if constexpr (ML == 0) {
        #pragma unroll
        for (int k = 0; k < 8; ++k) {
            const int kp = k ^ MK;
            if (k < kp) {
                const bool p0 = __popc(k  & RK) & 1;
                const bool p1 = __popc(kp & RK) & 1;
                u64 x0r = XR[k],  x0i = XI[k];
                u64 x1r = XR[kp], x1i = XI[kp];
                u64 a = x0r, b = x0i;
                upd(a, b, x1r, x1i, g, p0); XR[k]  = a; XI[k]  = b;
                u64 c = x1r, d = x1i;
                upd(c, d, x0r, x0i, g, p1); XR[kp] = c; XI[kp] = d;
            }
        }
    } else if constexpr (MK == 0) {
        #pragma unroll
        for (int k = 0; k < 8; ++k) {
            const u64 pr = __shfl_xor_sync(FULLMASK, XR[k], ML);
            const u64 pi = __shfl_xor_sync(FULLMASK, XI[k], ML);
            const bool p0 = __popc(k & RK) & 1;
            upd(XR[k], XI[k], pr, pi, g, p0);
        }
    } else {
        #pragma unroll
        for (int k = 0; k < 8; ++k) {
            const int kp = k ^ MK;
            if (k < kp) {
                const u64 p0r = __shfl_xor_sync(FULLMASK, XR[kp], ML);
                const u64 p0i = __shfl_xor_sync(FULLMASK, XI[kp], ML);
                const u64 p1r = __shfl_xor_sync(FULLMASK, XR[k],  ML);
                const u64 p1i = __shfl_xor_sync(FULLMASK, XI[k],  ML);
                const bool q0 = __popc(k  & RK) & 1;
                const bool q1 = __popc(kp & RK) & 1;
                upd(XR[k],  XI[k],  p0r, p0i, g, q0);
                upd(XR[kp], XI[kp], p1r, p1i, g, q1);
            }
        }
    }
}

// half-crossing gate (mask has bit1 + pack bit): partner = swap(X[k^MK]).
// Roles for our two instances: RH=1, RK=0, RL=0, RW templated.
template<int MK, int RW>
__device__ __forceinline__ void g_halfswap(u64 (&XR)[8], u64 (&XI)[8],
                                           float Ar, float Ai, float Br, float Bi,
                                           int lane, int w) {
    const GC g = make_gc<RW, 1, 0, 0>(Ar, Ai, Br, Bi, lane, w);
    #pragma unroll
    for (int k = 0; k < 8; ++k) {
        const int kp = k ^ MK;
        if (k < kp) {
            u64 x0r = XR[k],  x0i = XI[k];
            u64 x1r = XR[kp], x1i = XI[kp];
            u64 a = x0r, b = x0i;
            upd(a, b, sw2(x1r), sw2(x1i), g, false); XR[k]  = a; XI[k]  = b;
            u64 c = x1r, d = x1i;
            upd(c, d, sw2(x0r), sw2(x0i), g, false); XR[kp] = c; XI[kp] = d;
        }
    }
}

// cross-warp gate via smem; ROLE = warp bit only (sign warp-uniform).
// PKX: pack xor; SWAP: half-swap of partner pack.
template<int PKX, int SWAP>
__device__ __forceinline__ void g_cross(u64 (&XR)[8], u64 (&XI)[8],
                                        float Ar, float Ai, float Br, float Bi,
                                        int lane, int w,
                                        u64 (&sR)[2][8][32], u64 (&sI)[2][8][32]) {
    __syncthreads();
    #pragma unroll
    for (int k = 0; k < 8; ++k) { sR[w][k][lane] = XR[k]; sI[w][k][lane] = XI[k]; }
    __syncthreads();
    const float AiL = w ? Ai : -Ai;
    const float BrL = w ? Br : -Br;
    const u64 AK  = pk2(AiL, AiL), NAK = pk2(-AiL, -AiL);
    const u64 BK  = pk2(BrL, BrL);
    const u64 AR2 = pk2(Ar, Ar), BI2 = pk2(Bi, Bi), NBI2 = pk2(-Bi, -Bi);
    #pragma unroll
    for (int k = 0; k < 8; ++k) {
        u64 pr = sR[w ^ 1][k ^ PKX][lane];
        u64 pi = sI[w ^ 1][k ^ PKX][lane];
        if (SWAP) { pr = sw2(pr); pi = sw2(pi); }
        const u64 nr = f2fma(NBI2, pi, f2fma(BK, pr, f2fma(AK,  XI[k], f2mul(AR2, XR[k]))));
        const u64 ni = f2fma(BI2,  pr, f2fma(BK, pi, f2fma(NAK, XR[k], f2mul(AR2, XI[k]))));
        XR[k] = nr; XI[k] = ni;
    }
}

__global__ void __launch_bounds__(64)
cqv_kernel(const float* __restrict__ x,          // (2048, 49)
           const float* __restrict__ theta,      // (30,)
           const float* __restrict__ alpha_raw,  // (49,)
           const float* __restrict__ beta_raw,   // (49,)
           const float* __restrict__ head_w,     // (1, 10)
           const float* __restrict__ head_b,     // (1,)
           const float* __restrict__ logit_scale,// scalar
           float* __restrict__ out)              // (2048,)
{
    __shared__ float cg[64];
    __shared__ float sg[64];
    __shared__ float fAr[20], fAi[20], fBr[20], fBi[20];
    __shared__ u64 sR[2][8][32];
    __shared__ u64 sI[2][8][32];
    __shared__ float partial[2];

    const int t = threadIdx.x;
    const int w = t >> 5;
    const int lane = t & 31;
    const int sample = blockIdx.x;

    // ---- Phase A: 60 half-angle sincos (one per thread) ----
    if (t < 60) {
        const int b = t / 20;
        const int k = t - 20 * b;
        float half;
        if (k < 10) {
            const int f = b * 10 + k;                 // f <= 29 < 49
            const float a = alpha_raw[f];
            const float sp = fmaxf(a, 0.f) + log1pf(expf(-fabsf(a))) + 1e-6f;
            const float bt = tanhf(beta_raw[f]);
            half = 0.5f * PI_F * (sp * x[sample * INPUT_DIM + f] + bt);
        } else {
            half = 0.5f * theta[b * 10 + (k - 10)];
        }
        float s_, c_;
        sincosf(half, &s_, &c_);
        cg[t] = c_;
        sg[t] = s_;
    }
    __syncthreads();

    // ---- fused SU(2) coefficients for layers 2,3 (20 gates) ----
    if (t < 20) {
        const int b = 1 + t / 10;
        const int q = t - 10 * (b - 1);
        const float cy = cg[b * 20 + q],      sy = sg[b * 20 + q];
        const float cx = cg[b * 20 + 10 + q], sx = sg[b * 20 + 10 + q];
        fAr[t] =  cx * cy;
        fAi[t] = -sx * sy;
        fBr[t] =  cx * sy;
        fBi[t] = -sx * cy;
    }
    __syncthreads();

    // ---- Layer 1: product state (A = I), fused RX*RY from |0>, packed ----
    u64 XR[8], XI[8];
    {
        // per-thread scalar factor: qubit 0 (warp bit) and qubits 5-9 (lane bits)
        float lfr, lfi;
        {
            const float cy = cg[0], sy = sg[0];
            const float cx = cg[10], sx = sg[10];
            lfr =  cx * (w ? sy : cy);
            lfi = -sx * (w ? cy : sy);
        }
        #pragma unroll
        for (int q = 5; q < 10; ++q) {
            const float cy = cg[q],      sy = sg[q];
            const float cx = cg[10 + q], sx = sg[10 + q];
            const int bbit = (lane >> (q - 5)) & 1;
            const float fre =  cx * (bbit ? sy : cy);
            const float fim = -sx * (bbit ? cy : sy);
            const float nr = lfr * fre - lfi * fim;
            const float ni = lfr * fim + lfi * fre;
            lfr = nr; lfi = ni;
        }
        // qubit 1 -> packed half
        {
            const float cy = cg[1],  sy = sg[1];
            const float cx = cg[11], sx = sg[11];
            const float f0r = cx * cy, f0i = -sx * sy;
            const float f1r = cx * sy, f1i = -sx * cy;
            const float h0r = lfr * f0r - lfi * f0i;
            const float h0i = lfr * f0i + lfi * f0r;
            const float h1r = lfr * f1r - lfi * f1i;
            const float h1i = lfr * f1i + lfi * f1r;
            XR[0] = pk2(h0r, h1r);
            XI[0] = pk2(h0i, h1i);
        }
        // qubits 2,3,4 -> pack bits 0,1,2 (doubling, packed math)
        #pragma unroll
        for (int kk = 0; kk < 3; ++kk) {
            const int q = 2 + kk;
            const float cy = cg[q],      sy = sg[q];
            const float cx = cg[10 + q], sx = sg[10 + q];
            const u64 F0R  = pk2(cx * cy,  cx * cy);
            const u64 F0I  = pk2(-sx * sy, -sx * sy);
            const u64 NF0I = pk2(sx * sy,  sx * sy);
            const u64 F1R  = pk2(cx * sy,  cx * sy);
            const u64 F1I  = pk2(-sx * cy, -sx * cy);
            const u64 NF1I = pk2(sx * cy,  sx * cy);
            #pragma unroll
            for (int r = 0; r < 4; ++r) {
                if (r < (1 << kk)) {
                    const u64 br_ = XR[r], bi_ = XI[r];
                    XR[r + (1 << kk)] = f2fma(NF1I, bi_, f2mul(F1R, br_));
                    XI[r + (1 << kk)] = f2fma(F1I,  br_, f2mul(F1R, bi_));
                    XR[r] = f2fma(NF0I, bi_, f2mul(F0R, br_));
                    XI[r] = f2fma(F0I,  br_, f2mul(F0R, bi_));
                }
            }
        }
    }
    // layer-1 CNOT chain: frame A -> L (free).

    // ---- Layer 2 (A = L): m_q = e_q^e_{q+1}; role_q = bits[0..q] ----
    #define GP(IDX, MK, ML, RW, RH, RK, RL) \
        g_packed<MK, ML, RW, RH, RK, RL>(XR, XI, fAr[IDX], fAi[IDX], fBr[IDX], fBi[IDX], lane, w)
    g_cross<0, 1>(XR, XI, fAr[0], fAi[0], fBr[0], fBi[0], lane, w, sR, sI);   // M=0x003
    g_halfswap<1, 1>(XR, XI, fAr[1], fAi[1], fBr[1], fBi[1], lane, w);         // M=0x006, R=0x003
    GP(2, 3, 0,    1, 1, 1, 0);      // M=0x00C R=0x007
    GP(3, 6, 0,    1, 1, 3, 0);      // M=0x018 R=0x00F
    GP(4, 4, 1,    1, 1, 7, 0);      // M=0x030 R=0x01F
    GP(5, 0, 3,    1, 1, 7, 1);      // M=0x060 R=0x03F
    GP(6, 0, 6,    1, 1, 7, 3);      // M=0x0C0 R=0x07F
    GP(7, 0, 12,   1, 1, 7, 7);      // M=0x180 R=0x0FF
    GP(8, 0, 24,   1, 1, 7, 15);     // M=0x300 R=0x1FF
    GP(9, 0, 16,   1, 1, 7, 31);     // M=0x200 R=0x3FF
    // layer-2 CNOT chain: A -> L^2 (free).

    // ---- Layer 3 (A = L^2): m_q = e_q^e_{q+2}; role_q = {q,q-2,...} ----
    g_cross<1, 0>(XR, XI, fAr[10], fAi[10], fBr[10], fBi[10], lane, w, sR, sI); // M=0x005
    g_halfswap<2, 0>(XR, XI, fAr[11], fAi[11], fBr[11], fBi[11], lane, w);      // M=0x00A, R=0x002
    GP(12, 5, 0,   1, 0, 1, 0);      // M=0x014 R=0x005
    GP(13, 2, 1,   0, 1, 2, 0);      // M=0x028 R=0x00A
    GP(14, 4, 2,   1, 0, 5, 0);      // M=0x050 R=0x015
    GP(15, 0, 5,   0, 1, 2, 1);      // M=0x0A0 R=0x02A
    GP(16, 0, 10,  1, 0, 5, 2);      // M=0x140 R=0x055
    GP(17, 0, 20,  0, 1, 2, 5);      // M=0x280 R=0x0AA
    GP(18, 0, 8,   1, 0, 5, 10);     // M=0x100 R=0x155
    GP(19, 0, 16,  0, 1, 2, 21);     // M=0x200 R=0x2AA
    #undef GP
    // layer-3 CNOT chain: A -> L^3 (free).

    // ---- Readout: bit_q = parity(row_q(L^3) & i), decomposed w/reg/lane ----
    const int RWq[10] = {1, 1, 0, 0, 1, 1, 0, 0, 1, 1};
    const int RLq[10] = {0, 0, 0, 0, 0, 0x01, 0x03, 0x06, 0x0C, 0x19};

    float wl[10];
    #pragma unroll
    for (int q = 0; q < 10; ++q) {
        const float hw = head_w[q];
        const int sgn = (__popc(lane & RLq[q]) ^ (RWq[q] & w)) & 1;
        wl[q] = sgn ? -hw : hw;
    }
    const float u0 = wl[0];          // reg mask 0x0 (constant)
    const float u1 = wl[1];          // 0x1
    const float u2 = wl[2] + wl[6];  // 0x3
    const float u3 = wl[3] + wl[7];  // 0x6
    const float u4 = wl[4] + wl[8];  // 0xC
    const float u5 = wl[5] + wl[9];  // 0x9

    // coefficient per 4-bit reg index r = (k<<1)|h (signs fold at compile time)
    float c16[16];
    #pragma unroll
    for (int r = 0; r < 16; ++r) {
        float coef = u0;
        coef += (__popc(r & 0x1) & 1) ? -u1 : u1;
        coef += (__popc(r & 0x3) & 1) ? -u2 : u2;
        coef += (__popc(r & 0x6) & 1) ? -u3 : u3;
        coef += (__popc(r & 0xC) & 1) ? -u4 : u4;
        coef += (__popc(r & 0x9) & 1) ? -u5 : u5;
        c16[r] = coef;
    }

    u64 acc2 = pk2(0.f, 0.f);
    #pragma unroll
    for (int k = 0; k < 8; ++k) {
        const u64 P = f2fma(XI[k], XI[k], f2mul(XR[k], XR[k]));
        acc2 = f2fma(P, pk2(c16[2 * k], c16[2 * k + 1]), acc2);
    }
    float aLo, aHi;
    up2(acc2, aLo, aHi);
    float acc = aLo + aHi;
    #pragma unroll
    for (int off = 16; off > 0; off >>= 1)
        acc += __shfl_xor_sync(FULLMASK, acc, off);

    if (lane == 0) partial[w] = acc;
    __syncthreads();

    if (t == 0) {
        const float raw = partial[0] + partial[1] + head_b[0];
        const float scale = fminf(fmaxf(logit_scale[0], 0.5f), 80.0f);
        float v = scale * raw;
        v = fminf(fmaxf(v, -30.0f), 30.0f);
        out[sample] = v;
    }
}

extern "C" void kernel_launch(void* const* d_in, const int* in_sizes, int n_in,
                              void* d_out, int out_size) {
    (void)in_sizes; (void)n_in; (void)out_size;
    const float* x           = (const float*)d_in[0];
    const float* theta       = (const float*)d_in[1];
    const float* alpha_raw   = (const float*)d_in[2];
    const float* beta_raw    = (const float*)d_in[3];
    const float* head_w      = (const float*)d_in[4];
    const float* head_b      = (const float*)d_in[5];
    const float* logit_scale = (const float*)d_in[6];
    float* out = (float*)d_out;

    cqv_kernel<<<BATCH, 64>>>(x, theta, alpha_raw, beta_raw,
                              head_w, head_b, logit_scale, out);
}